// round 9
// baseline (speedup 1.0000x reference)
#include <cuda_runtime.h>
#include <cuda_bf16.h>
#include <cstdint>

// Problem constants
#define BB 2
#define LL 2048
#define DD 1024
#define NH 16
#define HD 64
#define MM (BB*LL)      // 4096
#define N3 (3*DD)       // 3072
#define KK DD           // 1024

typedef unsigned long long u64;
typedef unsigned int u32;

// ---- tf32 mma.sync helpers ----
__device__ __forceinline__ u32 f2tf32(float f) {
    u32 r; asm("cvt.rna.tf32.f32 %0, %1;" : "=r"(r) : "f"(f)); return r;
}
__device__ __forceinline__ void mma_tf32(float& d0, float& d1, float& d2, float& d3,
                                         u32 a0, u32 a1, u32 a2, u32 a3,
                                         u32 b0, u32 b1) {
    asm volatile(
        "mma.sync.aligned.m16n8k8.row.col.f32.tf32.tf32.f32 "
        "{%0,%1,%2,%3}, {%4,%5,%6,%7}, {%8,%9}, {%0,%1,%2,%3};"
        : "+f"(d0), "+f"(d1), "+f"(d2), "+f"(d3)
        : "r"(a0), "r"(a1), "r"(a2), "r"(a3), "r"(b0), "r"(b1));
}
__device__ __forceinline__ float ex2(float x) {
    float y; asm("ex2.approx.f32 %0, %1;" : "=f"(y) : "f"(x)); return y;
}
__device__ __forceinline__ u32 smem_u32(const void* p) {
    u32 a;
    asm("{ .reg .u64 t; cvta.to.shared.u64 t, %1; cvt.u32.u64 %0, t; }" : "=r"(a) : "l"(p));
    return a;
}
// ldmatrix x4: four 8x(16B) matrices; for fp32 data each matrix is an 8x4 f32
// quadrant == one tf32 mma fragment quadrant.
__device__ __forceinline__ void ldsm_x4(u32& r0, u32& r1, u32& r2, u32& r3, u32 addr) {
    asm volatile("ldmatrix.sync.aligned.m8n8.x4.shared.b16 {%0,%1,%2,%3}, [%4];"
                 : "=r"(r0), "=r"(r1), "=r"(r2), "=r"(r3) : "r"(addr));
}

// Scratch for qkv = x @ W^T + b : [4096, 3072] fp32
__device__ float g_qkv[(size_t)MM * N3];

// ---------------------------------------------------------------------------
// Kernel 1: QKV GEMM, mma.sync tf32, double-buffered K-chunks of 16, ldmatrix.
// (unchanged from R7)
// ---------------------------------------------------------------------------
#define GSTR 20

__global__ __launch_bounds__(256) void qkv_gemm_mma(
    const float* __restrict__ x,
    const float* __restrict__ W,
    const float* __restrict__ bias,
    float* __restrict__ C)
{
    __shared__ u32 sX[2 * 128 * GSTR];
    __shared__ u32 sW[2 * 128 * GSTR];
    __shared__ float sBias[128];

    const int bm = blockIdx.y * 128;
    const int bn = blockIdx.x * 128;
    const int tid  = threadIdx.x;
    const int wid  = tid >> 5;
    const int lane = tid & 31;
    const int wm = (wid >> 2) * 64;
    const int wn = (wid & 3) * 32;
    const int lr = lane >> 2;
    const int lc = lane & 3;

    const int l_row = tid >> 1;
    const int l_f4  = tid & 1;

    const u32 sXa = smem_u32(sX);
    const u32 sWa = smem_u32(sW);

    const int lm  = lane >> 3;
    const int lrw = lane & 7;
    const int a_row = (lm & 1) * 8 + lrw;
    const int a_col = (lm >> 1) * 4;
    const int b_nt  = lm >> 1;
    const int b_col = (lm & 1) * 4;

    float d[4][4][4];
#pragma unroll
    for (int mt = 0; mt < 4; mt++)
#pragma unroll
        for (int nt = 0; nt < 4; nt++)
#pragma unroll
            for (int r = 0; r < 4; r++) d[mt][nt][r] = 0.f;

    if (tid < 128) sBias[tid] = bias[bn + tid];

    float4 px[2], pw[2];
#pragma unroll
    for (int i = 0; i < 2; i++) {
        int f4 = l_f4 + i * 2;
        px[i] = *(const float4*)(x + (size_t)(bm + l_row) * KK + f4 * 4);
        pw[i] = *(const float4*)(W + (size_t)(bn + l_row) * KK + f4 * 4);
    }
#pragma unroll
    for (int i = 0; i < 2; i++) {
        int f4 = l_f4 + i * 2;
        *(uint4*)&sX[l_row * GSTR + f4 * 4] =
            make_uint4(f2tf32(px[i].x), f2tf32(px[i].y), f2tf32(px[i].z), f2tf32(px[i].w));
        *(uint4*)&sW[l_row * GSTR + f4 * 4] =
            make_uint4(f2tf32(pw[i].x), f2tf32(pw[i].y), f2tf32(pw[i].z), f2tf32(pw[i].w));
    }
    __syncthreads();

    for (int c = 0; c < KK / 16; c++) {
        if (c + 1 < KK / 16) {
            const int k0 = (c + 1) * 16;
#pragma unroll
            for (int i = 0; i < 2; i++) {
                int f4 = l_f4 + i * 2;
                px[i] = *(const float4*)(x + (size_t)(bm + l_row) * KK + k0 + f4 * 4);
                pw[i] = *(const float4*)(W + (size_t)(bn + l_row) * KK + k0 + f4 * 4);
            }
        }

        const u32 bufX = sXa + (u32)((c & 1) * 128 * GSTR * 4);
        const u32 bufW = sWa + (u32)((c & 1) * 128 * GSTR * 4);

#pragma unroll
        for (int ks = 0; ks < 2; ks++) {
            const int kk = ks * 8;
            u32 af[4][4];
            u32 bf[4][2];
#pragma unroll
            for (int mt = 0; mt < 4; mt++) {
                u32 addr = bufX + (u32)(((wm + mt * 16 + a_row) * GSTR + kk + a_col) * 4);
                ldsm_x4(af[mt][0], af[mt][1], af[mt][2], af[mt][3], addr);
            }
#pragma unroll
            for (int np = 0; np < 2; np++) {
                u32 addr = bufW + (u32)(((wn + (np * 2 + b_nt) * 8 + lrw) * GSTR + kk + b_col) * 4);
                ldsm_x4(bf[np * 2][0], bf[np * 2][1], bf[np * 2 + 1][0], bf[np * 2 + 1][1], addr);
            }
#pragma unroll
            for (int mt = 0; mt < 4; mt++)
#pragma unroll
                for (int nt = 0; nt < 4; nt++)
                    mma_tf32(d[mt][nt][0], d[mt][nt][1], d[mt][nt][2], d[mt][nt][3],
                             af[mt][0], af[mt][1], af[mt][2], af[mt][3],
                             bf[nt][0], bf[nt][1]);
        }

        if (c + 1 < KK / 16) {
            u32* dX = sX + ((c + 1) & 1) * 128 * GSTR;
            u32* dW = sW + ((c + 1) & 1) * 128 * GSTR;
#pragma unroll
            for (int i = 0; i < 2; i++) {
                int f4 = l_f4 + i * 2;
                *(uint4*)&dX[l_row * GSTR + f4 * 4] =
                    make_uint4(f2tf32(px[i].x), f2tf32(px[i].y), f2tf32(px[i].z), f2tf32(px[i].w));
                *(uint4*)&dW[l_row * GSTR + f4 * 4] =
                    make_uint4(f2tf32(pw[i].x), f2tf32(pw[i].y), f2tf32(pw[i].z), f2tf32(pw[i].w));
            }
        }
        __syncthreads();
    }

#pragma unroll
    for (int mt = 0; mt < 4; mt++) {
        const int r0 = bm + wm + mt * 16 + lr;
#pragma unroll
        for (int nt = 0; nt < 4; nt++) {
            const int cl = wn + nt * 8 + lc * 2;
            float2 v0, v1;
            v0.x = d[mt][nt][0] + sBias[cl];
            v0.y = d[mt][nt][1] + sBias[cl + 1];
            v1.x = d[mt][nt][2] + sBias[cl];
            v1.y = d[mt][nt][3] + sBias[cl + 1];
            *(float2*)(C + (size_t)r0 * N3 + bn + cl) = v0;
            *(float2*)(C + (size_t)(r0 + 8) * N3 + bn + cl) = v1;
        }
    }
}

// ---------------------------------------------------------------------------
// Kernel 2: flash attention, mma.sync tf32, kv-tile 32.
// K double-buffered; V stored TRANSPOSED (single buffer) -> ldmatrix B frags;
// P staged through per-warp smem -> ldmatrix A frags (no shuffles).
// ---------------------------------------------------------------------------
#define KSTR 68
#define VTSTR 36
#define PSTR 36
#define KV 32

__global__ __launch_bounds__(256, 2) void attn_mma(
    const float* __restrict__ qkv,   // [MM, N3]
    float* __restrict__ out)         // [MM, DD]
{
    // pool: sK (2 parities) | sVT | sP  = 4352 + 2304 + 4608 u32 = 45056 B
    __shared__ u32 pool[2 * KV * KSTR + 64 * VTSTR + 128 * PSTR];
    u32* sK  = pool;
    u32* sVT = pool + 2 * KV * KSTR;          // [d=64][kv=32], stride 36
    u32* sP  = sVT + 64 * VTSTR;              // [q=128][kv=32], stride 36
    const u32 sKa  = smem_u32(sK);
    const u32 sVTa = smem_u32(sVT);
    const u32 sPa  = smem_u32(sP);

    const int qtile = blockIdx.x;
    const int h     = blockIdx.y;
    const int b     = blockIdx.z;
    const int tid   = threadIdx.x;
    const int wid   = tid >> 5;
    const int lane  = tid & 31;
    const int lr    = lane >> 2;
    const int lc    = lane & 3;
    const int lm    = lane >> 3;
    const int lrw   = lane & 7;

    const float qs = 0.18033688011110793f;  // 0.125 * log2(e)

    const int l_row = tid >> 3;          // 0..31 (kv row)
    const int l_f4h = tid & 7;           // 0..7

    // ---- Q fragments resident ----
    const int row0 = qtile * 128 + wid * 16;
    const float* q0 = qkv + ((size_t)(b * LL + row0 + lr)) * N3 + h * HD;
    const float* q1 = q0 + 8 * (size_t)N3;
    u32 qa[8][4];
#pragma unroll
    for (int kst = 0; kst < 8; kst++) {
        int kk = kst * 8;
        qa[kst][0] = f2tf32(q0[kk + lc    ] * qs);
        qa[kst][1] = f2tf32(q1[kk + lc    ] * qs);
        qa[kst][2] = f2tf32(q0[kk + lc + 4] * qs);
        qa[kst][3] = f2tf32(q1[kk + lc + 4] * qs);
    }

    float o[8][4];
#pragma unroll
    for (int dt = 0; dt < 8; dt++)
#pragma unroll
        for (int r = 0; r < 4; r++) o[dt][r] = 0.f;
    float m_a = -1e30f, m_b = -1e30f;
    float l_a = 0.f,    l_b = 0.f;

    const float* kvbase = qkv + (size_t)b * LL * N3 + DD + h * HD;

    float4 pk[2], pv[2];
    // prefetch + store tile 0
#pragma unroll
    for (int i = 0; i < 2; i++) {
        const float* kp = kvbase + (size_t)l_row * N3 + (l_f4h + i * 8) * 4;
        pk[i] = *(const float4*)kp;
        pv[i] = *(const float4*)(kp + DD);
    }
#pragma unroll
    for (int i = 0; i < 2; i++) {
        int f4 = l_f4h + i * 8;
        *(uint4*)&sK[l_row * KSTR + f4 * 4] =
            make_uint4(f2tf32(pk[i].x), f2tf32(pk[i].y), f2tf32(pk[i].z), f2tf32(pk[i].w));
        int d0 = f4 * 4;
        sVT[(d0 + 0) * VTSTR + l_row] = f2tf32(pv[i].x);
        sVT[(d0 + 1) * VTSTR + l_row] = f2tf32(pv[i].y);
        sVT[(d0 + 2) * VTSTR + l_row] = f2tf32(pv[i].z);
        sVT[(d0 + 3) * VTSTR + l_row] = f2tf32(pv[i].w);
    }
    __syncthreads();

    const int NT = LL / KV;   // 64
    for (int kt = 0; kt < NT; kt++) {
        // prefetch next tile into regs
        if (kt + 1 < NT) {
            const float* tb = kvbase + (size_t)((kt + 1) * KV) * N3;
#pragma unroll
            for (int i = 0; i < 2; i++) {
                const float* kp = tb + (size_t)l_row * N3 + (l_f4h + i * 8) * 4;
                pk[i] = *(const float4*)kp;
                pv[i] = *(const float4*)(kp + DD);
            }
        }

        const u32 bufK = sKa + (u32)((kt & 1) * KV * KSTR * 4);

        // ---- S = Q K^T ----
        float s[4][4];
#pragma unroll
        for (int nt = 0; nt < 4; nt++)
#pragma unroll
            for (int r = 0; r < 4; r++) s[nt][r] = 0.f;

#pragma unroll
        for (int kst = 0; kst < 8; kst++) {
            const int kk = kst * 8;
            u32 bf[4][2];
#pragma unroll
            for (int np = 0; np < 2; np++) {
                int nt0 = np * 2 + (lm >> 1);
                u32 addr = bufK + (u32)(((nt0 * 8 + lrw) * KSTR + kk + (lm & 1) * 4) * 4);
                ldsm_x4(bf[np * 2][0], bf[np * 2][1], bf[np * 2 + 1][0], bf[np * 2 + 1][1], addr);
            }
#pragma unroll
            for (int nt = 0; nt < 4; nt++)
                mma_tf32(s[nt][0], s[nt][1], s[nt][2], s[nt][3],
                         qa[kst][0], qa[kst][1], qa[kst][2], qa[kst][3],
                         bf[nt][0], bf[nt][1]);
        }

        // ---- online softmax ----
        float mx_a = -1e30f, mx_b = -1e30f;
#pragma unroll
        for (int nt = 0; nt < 4; nt++) {
            mx_a = fmaxf(mx_a, fmaxf(s[nt][0], s[nt][1]));
            mx_b = fmaxf(mx_b, fmaxf(s[nt][2], s[nt][3]));
        }
        mx_a = fmaxf(mx_a, __shfl_xor_sync(0xffffffffu, mx_a, 1));
        mx_a = fmaxf(mx_a, __shfl_xor_sync(0xffffffffu, mx_a, 2));
        mx_b = fmaxf(mx_b, __shfl_xor_sync(0xffffffffu, mx_b, 1));
        mx_b = fmaxf(mx_b, __shfl_xor_sync(0xffffffffu, mx_b, 2));

        float nm_a = fmaxf(m_a, mx_a);
        float nm_b = fmaxf(m_b, mx_b);
        float ca = ex2(m_a - nm_a);
        float cb = ex2(m_b - nm_b);
        m_a = nm_a; m_b = nm_b;
        l_a *= ca;  l_b *= cb;
#pragma unroll
        for (int dt = 0; dt < 8; dt++) {
            o[dt][0] *= ca; o[dt][1] *= ca;
            o[dt][2] *= cb; o[dt][3] *= cb;
        }

        // ---- p = 2^(s-m); store P to per-warp smem in row-major (STS.64) ----
#pragma unroll
        for (int jt = 0; jt < 4; jt++) {
            float p0 = ex2(s[jt][0] - m_a);
            float p1 = ex2(s[jt][1] - m_a);
            float p2 = ex2(s[jt][2] - m_b);
            float p3 = ex2(s[jt][3] - m_b);
            l_a += p0 + p1;
            l_b += p2 + p3;
            uint2 lo = make_uint2(f2tf32(p0), f2tf32(p1));
            uint2 hi = make_uint2(f2tf32(p2), f2tf32(p3));
            *(uint2*)&sP[(wid * 16 + lr    ) * PSTR + jt * 8 + lc * 2] = lo;
            *(uint2*)&sP[(wid * 16 + 8 + lr) * PSTR + jt * 8 + lc * 2] = hi;
        }
        __syncwarp();

        // ---- O += P V : P A-frags and V B-frags both via ldmatrix ----
#pragma unroll
        for (int jt = 0; jt < 4; jt++) {
            u32 a0, a1, a2, a3;
            {
                u32 addr = sPa + (u32)(((wid * 16 + (lm & 1) * 8 + lrw) * PSTR
                                        + jt * 8 + (lm >> 1) * 4) * 4);
                ldsm_x4(a0, a1, a2, a3, addr);
            }
#pragma unroll
            for (int dp = 0; dp < 4; dp++) {
                u32 b00, b01, b10, b11;
                u32 addr = sVTa + (u32)(((dp * 16 + (lm >> 1) * 8 + lrw) * VTSTR
                                         + jt * 8 + (lm & 1) * 4) * 4);
                ldsm_x4(b00, b01, b10, b11, addr);
                mma_tf32(o[dp * 2][0], o[dp * 2][1], o[dp * 2][2], o[dp * 2][3],
                         a0, a1, a2, a3, b00, b01);
                mma_tf32(o[dp * 2 + 1][0], o[dp * 2 + 1][1], o[dp * 2 + 1][2], o[dp * 2 + 1][3],
                         a0, a1, a2, a3, b10, b11);
            }
        }

        __syncthreads();   // all warps done with sVT (and current K parity)

        // stage next tile: K -> other parity, V -> transposed (single buffer)
        if (kt + 1 < NT) {
            u32* dK = sK + ((kt + 1) & 1) * KV * KSTR;
#pragma unroll
            for (int i = 0; i < 2; i++) {
                int f4 = l_f4h + i * 8;
                *(uint4*)&dK[l_row * KSTR + f4 * 4] =
                    make_uint4(f2tf32(pk[i].x), f2tf32(pk[i].y), f2tf32(pk[i].z), f2tf32(pk[i].w));
                int d0 = f4 * 4;
                sVT[(d0 + 0) * VTSTR + l_row] = f2tf32(pv[i].x);
                sVT[(d0 + 1) * VTSTR + l_row] = f2tf32(pv[i].y);
                sVT[(d0 + 2) * VTSTR + l_row] = f2tf32(pv[i].z);
                sVT[(d0 + 3) * VTSTR + l_row] = f2tf32(pv[i].w);
            }
        }
        __syncthreads();
    }

    // ---- final reduce + normalize ----
    l_a += __shfl_xor_sync(0xffffffffu, l_a, 1);
    l_a += __shfl_xor_sync(0xffffffffu, l_a, 2);
    l_b += __shfl_xor_sync(0xffffffffu, l_b, 1);
    l_b += __shfl_xor_sync(0xffffffffu, l_b, 2);
    float inv_a = 1.f / l_a;
    float inv_b = 1.f / l_b;

    // ---- stage O to smem then coalesced store ----
    float* stage = (float*)pool;   // 128 x 68 floats = 34816 B <= pool size
    {
        const int ra = wid * 16 + lr;
        const int rb = ra + 8;
#pragma unroll
        for (int dt = 0; dt < 8; dt++) {
            float2 va, vb;
            va.x = o[dt][0] * inv_a; va.y = o[dt][1] * inv_a;
            vb.x = o[dt][2] * inv_b; vb.y = o[dt][3] * inv_b;
            *(float2*)&stage[ra * 68 + dt * 8 + lc * 2] = va;
            *(float2*)&stage[rb * 68 + dt * 8 + lc * 2] = vb;
        }
    }
    __syncthreads();
    {
        const int cr = tid >> 4;
        const int cc = tid & 15;
#pragma unroll
        for (int pass = 0; pass < 8; pass++) {
            int row = pass * 16 + cr;
            float4 v = *(const float4*)&stage[row * 68 + cc * 4];
            *(float4*)(out + ((size_t)(b * LL + qtile * 128 + row)) * DD + h * HD + cc * 4) = v;
        }
    }
}

// ---------------------------------------------------------------------------
extern "C" void kernel_launch(void* const* d_in, const int* in_sizes, int n_in,
                              void* d_out, int out_size)
{
    const float* x    = (const float*)d_in[0];
    const float* W    = (const float*)d_in[1];
    const float* bias = (const float*)d_in[2];
    float* out = (float*)d_out;

    float* qkv;
    cudaGetSymbolAddress((void**)&qkv, g_qkv);

    dim3 ggrid(N3 / 128, MM / 128);  // (24, 32)
    qkv_gemm_mma<<<ggrid, 256>>>(x, W, bias, qkv);

    dim3 agrid(LL / 128, NH, BB);    // (16, 16, 2)
    attn_mma<<<agrid, 256>>>(qkv, out);
}